// round 2
// baseline (speedup 1.0000x reference)
#include <cuda_runtime.h>
#include <math.h>

#define DM    128
#define DI    256
#define DS    16
#define DR    8
#define NB    16
#define LSEQ  4096
#define BL    (NB*LSEQ)

__device__ float g_xs[(size_t)BL*DI];
__device__ float g_z [(size_t)BL*DI];
__device__ float g_xc[(size_t)BL*DI];
__device__ float g_delta[(size_t)BL*DI];
__device__ float g_Bm[(size_t)BL*DS];
__device__ float g_Cm[(size_t)BL*DS];
__device__ float g_y [(size_t)BL*DI];

__device__ __forceinline__ float sigmoidf_(float v){ return 1.f/(1.f+__expf(-v)); }

// ============ Kernel 1: xz = u @ W_in  (M=65536, N=512, K=128) ============
__global__ __launch_bounds__(256) void k_inproj(const float* __restrict__ x,
                                                const float* __restrict__ Win)
{
    __shared__ float As[64][64];   // [k][m]
    __shared__ float Bs[64][64];   // [k][n]
    int tid = threadIdx.x;
    int ty = tid >> 4, tx = tid & 15;
    int mt = blockIdx.x;
    int n0 = blockIdx.y * 64;
    int b  = mt >> 6;
    int l0 = (mt * 64) & 4095;
    const float* xb = x + (size_t)b * DM * LSEQ;

    float acc[4][4];
#pragma unroll
    for (int i = 0; i < 4; i++)
#pragma unroll
        for (int j = 0; j < 4; j++) acc[i][j] = 0.f;

    for (int kc = 0; kc < 2; kc++) {
#pragma unroll
        for (int it = 0; it < 4; it++) {
            int fid = tid + it * 256;
            int r = fid >> 4, c4 = fid & 15;
            float4 v = *(const float4*)(xb + (size_t)(kc*64 + r) * LSEQ + l0 + c4*4);
            *(float4*)&As[r][c4*4] = v;
        }
#pragma unroll
        for (int it = 0; it < 4; it++) {
            int fid = tid + it * 256;
            int r = fid >> 4, c4 = fid & 15;
            float4 v = *(const float4*)(Win + (size_t)(kc*64 + r) * 512 + n0 + c4*4);
            *(float4*)&Bs[r][c4*4] = v;
        }
        __syncthreads();
#pragma unroll
        for (int kk = 0; kk < 64; kk++) {
            float4 a  = *(const float4*)&As[kk][ty*4];
            float4 bq = *(const float4*)&Bs[kk][tx*4];
            float av[4] = {a.x, a.y, a.z, a.w};
            float bv[4] = {bq.x, bq.y, bq.z, bq.w};
#pragma unroll
            for (int i = 0; i < 4; i++)
#pragma unroll
                for (int j = 0; j < 4; j++)
                    acc[i][j] = fmaf(av[i], bv[j], acc[i][j]);
        }
        __syncthreads();
    }
    float* dst = (n0 < DI) ? g_xs : g_z;
    int d0 = (n0 < DI) ? n0 : (n0 - DI);
#pragma unroll
    for (int i = 0; i < 4; i++) {
        size_t row = (size_t)(mt*64 + ty*4 + i) * DI + d0 + tx*4;
        *(float4*)(dst + row) = make_float4(acc[i][0], acc[i][1], acc[i][2], acc[i][3]);
    }
}

// ============ Kernel 2: causal depthwise conv k=4 + bias + silu ============
__global__ __launch_bounds__(256) void k_conv(const float* __restrict__ cw,
                                              const float* __restrict__ cb)
{
    __shared__ float sx[131][64];
    __shared__ float scw[4][64];
    __shared__ float scb[64];
    int tid = threadIdx.x;
    int d0 = blockIdx.x * 64;
    int l0 = blockIdx.y * 128;
    int b  = blockIdx.z;

    if (tid < 64) {
        scb[tid] = cb[d0 + tid];
#pragma unroll
        for (int k = 0; k < 4; k++) scw[k][tid] = cw[(d0 + tid) * 4 + k];
    }
    for (int fid = tid; fid < 131*16; fid += 256) {
        int r = fid >> 4, c4 = fid & 15;
        int l = l0 - 3 + r;
        float4 v = make_float4(0.f, 0.f, 0.f, 0.f);
        if (l >= 0)
            v = *(const float4*)(g_xs + (size_t)(b*LSEQ + l) * DI + d0 + c4*4);
        *(float4*)&sx[r][c4*4] = v;
    }
    __syncthreads();
#pragma unroll
    for (int it = 0; it < 32; it++) {
        int idx = tid + it * 256;
        int li = idx >> 6, di = idx & 63;
        float v = scb[di];
#pragma unroll
        for (int k = 0; k < 4; k++) v = fmaf(scw[k][di], sx[li + k][di], v);
        v = v * sigmoidf_(v);
        g_xc[(size_t)(b*LSEQ + l0 + li) * DI + d0 + di] = v;
    }
}

// ============ Kernel 3: dbl = xc@W_xproj; delta = softplus(dt@W_dt+b) ======
__global__ __launch_bounds__(160) void k_xproj(const float* __restrict__ Wxp,
                                               const float* __restrict__ Wdt,
                                               const float* __restrict__ bdt)
{
    __shared__ float As[64*65];
    __shared__ float Bs[64*40];
    __shared__ float dbl_s[64*41];
    __shared__ float Wdt_s[8*256];
    __shared__ float bdt_s[256];
    int tid = threadIdx.x;
    int ty = tid / 10, tx = tid % 10;
    int bl0 = blockIdx.x * 64;

    for (int i = tid; i < 2048; i += 160) Wdt_s[i] = Wdt[i];
    for (int i = tid; i < 256;  i += 160) bdt_s[i] = bdt[i];

    float acc[4][4];
#pragma unroll
    for (int i = 0; i < 4; i++)
#pragma unroll
        for (int j = 0; j < 4; j++) acc[i][j] = 0.f;

    for (int kc = 0; kc < 4; kc++) {
        for (int fid = tid; fid < 1024; fid += 160) {
            int m = fid >> 4, c4 = fid & 15;
            float4 v = *(const float4*)(g_xc + (size_t)(bl0 + m) * DI + kc*64 + c4*4);
            As[m*65 + c4*4 + 0] = v.x;  As[m*65 + c4*4 + 1] = v.y;
            As[m*65 + c4*4 + 2] = v.z;  As[m*65 + c4*4 + 3] = v.w;
        }
        for (int fid = tid; fid < 640; fid += 160) {
            int k = fid / 10, c4 = fid % 10;
            *(float4*)&Bs[k*40 + c4*4] = *(const float4*)(Wxp + (size_t)(kc*64 + k) * 40 + c4*4);
        }
        __syncthreads();
#pragma unroll
        for (int kk = 0; kk < 64; kk++) {
            float av[4];
#pragma unroll
            for (int i = 0; i < 4; i++) av[i] = As[(ty*4 + i)*65 + kk];
            float4 bq = *(const float4*)&Bs[kk*40 + tx*4];
            float bv[4] = {bq.x, bq.y, bq.z, bq.w};
#pragma unroll
            for (int i = 0; i < 4; i++)
#pragma unroll
                for (int j = 0; j < 4; j++)
                    acc[i][j] = fmaf(av[i], bv[j], acc[i][j]);
        }
        __syncthreads();
    }
#pragma unroll
    for (int i = 0; i < 4; i++)
#pragma unroll
        for (int j = 0; j < 4; j++)
            dbl_s[(ty*4 + i)*41 + tx*4 + j] = acc[i][j];
    __syncthreads();

    for (int idx = tid; idx < 1024; idx += 160) {
        int l = idx >> 4, n = idx & 15;
        g_Bm[(size_t)(bl0 + l) * DS + n] = dbl_s[l*41 + 8  + n];
        g_Cm[(size_t)(bl0 + l) * DS + n] = dbl_s[l*41 + 24 + n];
    }
    for (int idx = tid; idx < 64*256; idx += 160) {
        int l = idx >> 8, d = idx & 255;
        float a = bdt_s[d];
#pragma unroll
        for (int r = 0; r < 8; r++)
            a = fmaf(dbl_s[l*41 + r], Wdt_s[r*256 + d], a);
        float sp = (a > 20.f) ? a : log1pf(__expf(a));
        g_delta[(size_t)(bl0 + l) * DI + d] = sp;
    }
}

// ============ Kernel 4: selective scan, single pass over L=4096 ============
__global__ __launch_bounds__(64) void k_scan(const float* __restrict__ A_log,
                                             const float* __restrict__ Dpar)
{
    __shared__ float s_dt[64][8], s_xc[64][8], s_z[64][8];
    __shared__ float s_bm[64*16], s_cm[64*16];
    __shared__ float s_y[64][8];
    int tid = threadIdx.x;
    int dl = tid >> 3, np = tid & 7;
    int dg = blockIdx.x;
    int b  = blockIdx.y;
    int d  = dg*8 + dl;

    float A0 = -__expf(A_log[d*DS + np]);
    float A1 = -__expf(A_log[d*DS + np + 8]);
    float Dp = Dpar[d];
    float h0 = 0.f, h1 = 0.f;
    size_t baseD = (size_t)b * LSEQ * DI + dg*8;
    size_t baseN = (size_t)b * LSEQ * DS;

    for (int lc = 0; lc < 64; lc++) {
        int l0 = lc * 64;
        __syncthreads();
#pragma unroll
        for (int it = 0; it < 2; it++) {
            int fid = tid + it*64;
            int r = fid >> 1, c4 = fid & 1;
            size_t g = baseD + (size_t)(l0 + r) * DI + c4*4;
            *(float4*)&s_dt[r][c4*4] = *(const float4*)(g_delta + g);
            *(float4*)&s_xc[r][c4*4] = *(const float4*)(g_xc + g);
            *(float4*)&s_z [r][c4*4] = *(const float4*)(g_z + g);
        }
#pragma unroll
        for (int it = 0; it < 4; it++) {
            int fid = tid + it*64;
            *(float4*)&s_bm[fid*4] = *(const float4*)(g_Bm + baseN + (size_t)l0*DS + fid*4);
            *(float4*)&s_cm[fid*4] = *(const float4*)(g_Cm + baseN + (size_t)l0*DS + fid*4);
        }
        __syncthreads();
#pragma unroll 4
        for (int li = 0; li < 64; li++) {
            float dt = s_dt[li][dl];
            float xv = s_xc[li][dl];
            float b0 = s_bm[li*16 + np],     b1 = s_bm[li*16 + np + 8];
            float c0 = s_cm[li*16 + np],     c1 = s_cm[li*16 + np + 8];
            float e0 = __expf(dt * A0),      e1 = __expf(dt * A1);
            float du = dt * xv;
            h0 = fmaf(e0, h0, du * b0);
            h1 = fmaf(e1, h1, du * b1);
            float p = fmaf(h1, c1, h0 * c0);
            p += __shfl_xor_sync(0xffffffffu, p, 1, 8);
            p += __shfl_xor_sync(0xffffffffu, p, 2, 8);
            p += __shfl_xor_sync(0xffffffffu, p, 4, 8);
            if (np == 0) {
                float zz = s_z[li][dl];
                s_y[li][dl] = (p + xv * Dp) * (zz * sigmoidf_(zz));
            }
        }
        __syncthreads();
#pragma unroll
        for (int it = 0; it < 2; it++) {
            int fid = tid + it*64;
            int r = fid >> 1, c4 = fid & 1;
            *(float4*)(g_y + baseD + (size_t)(l0 + r) * DI + c4*4) = *(float4*)&s_y[r][c4*4];
        }
    }
}

// ============ Kernel 5: out = y @ W_out, transposed store out[b,c,w,h] =====
__global__ __launch_bounds__(256) void k_outproj(const float* __restrict__ Wout,
                                                 float* __restrict__ out)
{
    __shared__ float As[64*65];   // [m=h][k]; reused as [c][h] staging
    __shared__ float Bs[64][64];  // [k][n=c]
    int tid = threadIdx.x;
    int ty = tid >> 4, tx = tid & 15;
    int c0 = blockIdx.x * 64;
    int w  = blockIdx.y;
    int b  = blockIdx.z;

    float acc[4][4];
#pragma unroll
    for (int i = 0; i < 4; i++)
#pragma unroll
        for (int j = 0; j < 4; j++) acc[i][j] = 0.f;

    for (int kc = 0; kc < 4; kc++) {
#pragma unroll
        for (int it = 0; it < 4; it++) {
            int fid = tid + it*256;
            int m = fid >> 4, c4 = fid & 15;
            float4 v = *(const float4*)(g_y + (size_t)(b*LSEQ + m*64 + w) * DI + kc*64 + c4*4);
            As[m*65 + c4*4 + 0] = v.x;  As[m*65 + c4*4 + 1] = v.y;
            As[m*65 + c4*4 + 2] = v.z;  As[m*65 + c4*4 + 3] = v.w;
        }
#pragma unroll
        for (int it = 0; it < 4; it++) {
            int fid = tid + it*256;
            int r = fid >> 4, c4 = fid & 15;
            *(float4*)&Bs[r][c4*4] = *(const float4*)(Wout + (size_t)(kc*64 + r) * 128 + c0 + c4*4);
        }
        __syncthreads();
#pragma unroll
        for (int kk = 0; kk < 64; kk++) {
            float av[4];
#pragma unroll
            for (int i = 0; i < 4; i++) av[i] = As[(ty*4 + i)*65 + kk];
            float4 bq = *(const float4*)&Bs[kk][tx*4];
            float bv[4] = {bq.x, bq.y, bq.z, bq.w};
#pragma unroll
            for (int i = 0; i < 4; i++)
#pragma unroll
                for (int j = 0; j < 4; j++)
                    acc[i][j] = fmaf(av[i], bv[j], acc[i][j]);
        }
        __syncthreads();
    }
    // stage transposed: As[c][h]
#pragma unroll
    for (int i = 0; i < 4; i++)
#pragma unroll
        for (int j = 0; j < 4; j++)
            As[(tx*4 + j)*65 + ty*4 + i] = acc[i][j];
    __syncthreads();
    for (int fid = tid; fid < 1024; fid += 256) {
        int c = fid >> 4, c4 = fid & 15;
        float4 v;
        v.x = As[c*65 + c4*4 + 0]; v.y = As[c*65 + c4*4 + 1];
        v.z = As[c*65 + c4*4 + 2]; v.w = As[c*65 + c4*4 + 3];
        *(float4*)(out + ((size_t)(b*128 + c0 + c)*64 + w)*64 + c4*4) = v;
    }
}

extern "C" void kernel_launch(void* const* d_in, const int* in_sizes, int n_in,
                              void* d_out, int out_size) {
    const float* x     = (const float*)d_in[0];
    const float* Win   = (const float*)d_in[1];
    const float* cw    = (const float*)d_in[2];
    const float* cb    = (const float*)d_in[3];
    const float* Wxp   = (const float*)d_in[4];
    const float* Wdt   = (const float*)d_in[5];
    const float* bdt   = (const float*)d_in[6];
    const float* A_log = (const float*)d_in[7];
    const float* Dpar  = (const float*)d_in[8];
    const float* Wout  = (const float*)d_in[9];
    float* out = (float*)d_out;

    k_inproj <<<dim3(1024, 8), 256>>>(x, Win);
    k_conv   <<<dim3(4, 32, 16), 256>>>(cw, cb);
    k_xproj  <<<dim3(1024), 160>>>(Wxp, Wdt, bdt);
    k_scan   <<<dim3(32, 16), 64>>>(A_log, Dpar);
    k_outproj<<<dim3(2, 64, 16), 256>>>(Wout, out);
}

// round 3
// speedup vs baseline: 1.8858x; 1.8858x over previous
#include <cuda_runtime.h>
#include <math.h>

#define DM    128
#define DI    256
#define DS    16
#define DR    8
#define NB    16
#define LSEQ  4096
#define BL    (NB*LSEQ)
#define CT    64            // chunk length
#define NC    (LSEQ/CT)     // 64 chunks

// pad activation buffers by DI so t+1 prefetch at the very end stays in-bounds
__device__ float g_xs[(size_t)BL*DI + DI];
__device__ float g_z [(size_t)BL*DI + DI];
__device__ float g_xc[(size_t)BL*DI + DI];
__device__ float g_delta[(size_t)BL*DI + DI];
__device__ float g_Bm[(size_t)BL*DS];
__device__ float g_Cm[(size_t)BL*DS];
__device__ float g_y [(size_t)BL*DI];
// chunked-scan state: layout [b][c][d][n]
__device__ float g_hfin  [(size_t)NB*NC*DI*DS];
__device__ float g_P     [(size_t)NB*NC*DI*DS];
__device__ float g_hstart[(size_t)NB*NC*DI*DS];

__device__ __forceinline__ float sigmoidf_(float v){ return __fdividef(1.f, 1.f+__expf(-v)); }

// ============ Kernel 1: xz = u @ W_in  (M=65536, N=512, K=128) ============
__global__ __launch_bounds__(256) void k_inproj(const float* __restrict__ x,
                                                const float* __restrict__ Win)
{
    __shared__ float As[64][64];
    __shared__ float Bs[64][64];
    int tid = threadIdx.x;
    int ty = tid >> 4, tx = tid & 15;
    int mt = blockIdx.x;
    int n0 = blockIdx.y * 64;
    int b  = mt >> 6;
    int l0 = (mt * 64) & 4095;
    const float* xb = x + (size_t)b * DM * LSEQ;

    float acc[4][4];
#pragma unroll
    for (int i = 0; i < 4; i++)
#pragma unroll
        for (int j = 0; j < 4; j++) acc[i][j] = 0.f;

    for (int kc = 0; kc < 2; kc++) {
#pragma unroll
        for (int it = 0; it < 4; it++) {
            int fid = tid + it * 256;
            int r = fid >> 4, c4 = fid & 15;
            *(float4*)&As[r][c4*4] = *(const float4*)(xb + (size_t)(kc*64 + r) * LSEQ + l0 + c4*4);
        }
#pragma unroll
        for (int it = 0; it < 4; it++) {
            int fid = tid + it * 256;
            int r = fid >> 4, c4 = fid & 15;
            *(float4*)&Bs[r][c4*4] = *(const float4*)(Win + (size_t)(kc*64 + r) * 512 + n0 + c4*4);
        }
        __syncthreads();
#pragma unroll
        for (int kk = 0; kk < 64; kk++) {
            float4 a  = *(const float4*)&As[kk][ty*4];
            float4 bq = *(const float4*)&Bs[kk][tx*4];
            float av[4] = {a.x, a.y, a.z, a.w};
            float bv[4] = {bq.x, bq.y, bq.z, bq.w};
#pragma unroll
            for (int i = 0; i < 4; i++)
#pragma unroll
                for (int j = 0; j < 4; j++)
                    acc[i][j] = fmaf(av[i], bv[j], acc[i][j]);
        }
        __syncthreads();
    }
    float* dst = (n0 < DI) ? g_xs : g_z;
    int d0 = (n0 < DI) ? n0 : (n0 - DI);
#pragma unroll
    for (int i = 0; i < 4; i++) {
        size_t row = (size_t)(mt*64 + ty*4 + i) * DI + d0 + tx*4;
        *(float4*)(dst + row) = make_float4(acc[i][0], acc[i][1], acc[i][2], acc[i][3]);
    }
}

// ============ Kernel 2: causal depthwise conv k=4 + bias + silu ============
__global__ __launch_bounds__(256) void k_conv(const float* __restrict__ cw,
                                              const float* __restrict__ cb)
{
    __shared__ float sx[131][64];
    __shared__ float scw[4][64];
    __shared__ float scb[64];
    int tid = threadIdx.x;
    int d0 = blockIdx.x * 64;
    int l0 = blockIdx.y * 128;
    int b  = blockIdx.z;

    if (tid < 64) {
        scb[tid] = cb[d0 + tid];
#pragma unroll
        for (int k = 0; k < 4; k++) scw[k][tid] = cw[(d0 + tid) * 4 + k];
    }
    for (int fid = tid; fid < 131*16; fid += 256) {
        int r = fid >> 4, c4 = fid & 15;
        int l = l0 - 3 + r;
        float4 v = make_float4(0.f, 0.f, 0.f, 0.f);
        if (l >= 0)
            v = *(const float4*)(g_xs + (size_t)(b*LSEQ + l) * DI + d0 + c4*4);
        *(float4*)&sx[r][c4*4] = v;
    }
    __syncthreads();
#pragma unroll
    for (int it = 0; it < 32; it++) {
        int idx = tid + it * 256;
        int li = idx >> 6, di = idx & 63;
        float v = scb[di];
#pragma unroll
        for (int k = 0; k < 4; k++) v = fmaf(scw[k][di], sx[li + k][di], v);
        v = v * sigmoidf_(v);
        g_xc[(size_t)(b*LSEQ + l0 + li) * DI + d0 + di] = v;
    }
}

// ============ Kernel 3: dbl = xc@W_xproj; delta = softplus(dt@W_dt+b) ======
__global__ __launch_bounds__(160) void k_xproj(const float* __restrict__ Wxp,
                                               const float* __restrict__ Wdt,
                                               const float* __restrict__ bdt)
{
    __shared__ float As[64*65];
    __shared__ float Bs[64*40];
    __shared__ float dbl_s[64*41];
    __shared__ float Wdt_s[8*256];
    __shared__ float bdt_s[256];
    int tid = threadIdx.x;
    int ty = tid / 10, tx = tid % 10;
    int bl0 = blockIdx.x * 64;

    for (int i = tid; i < 2048; i += 160) Wdt_s[i] = Wdt[i];
    for (int i = tid; i < 256;  i += 160) bdt_s[i] = bdt[i];

    float acc[4][4];
#pragma unroll
    for (int i = 0; i < 4; i++)
#pragma unroll
        for (int j = 0; j < 4; j++) acc[i][j] = 0.f;

    for (int kc = 0; kc < 4; kc++) {
        for (int fid = tid; fid < 1024; fid += 160) {
            int m = fid >> 4, c4 = fid & 15;
            float4 v = *(const float4*)(g_xc + (size_t)(bl0 + m) * DI + kc*64 + c4*4);
            As[m*65 + c4*4 + 0] = v.x;  As[m*65 + c4*4 + 1] = v.y;
            As[m*65 + c4*4 + 2] = v.z;  As[m*65 + c4*4 + 3] = v.w;
        }
        for (int fid = tid; fid < 640; fid += 160) {
            int k = fid / 10, c4 = fid % 10;
            *(float4*)&Bs[k*40 + c4*4] = *(const float4*)(Wxp + (size_t)(kc*64 + k) * 40 + c4*4);
        }
        __syncthreads();
#pragma unroll
        for (int kk = 0; kk < 64; kk++) {
            float av[4];
#pragma unroll
            for (int i = 0; i < 4; i++) av[i] = As[(ty*4 + i)*65 + kk];
            float4 bq = *(const float4*)&Bs[kk*40 + tx*4];
            float bv[4] = {bq.x, bq.y, bq.z, bq.w};
#pragma unroll
            for (int i = 0; i < 4; i++)
#pragma unroll
                for (int j = 0; j < 4; j++)
                    acc[i][j] = fmaf(av[i], bv[j], acc[i][j]);
        }
        __syncthreads();
    }
#pragma unroll
    for (int i = 0; i < 4; i++)
#pragma unroll
        for (int j = 0; j < 4; j++)
            dbl_s[(ty*4 + i)*41 + tx*4 + j] = acc[i][j];
    __syncthreads();

    for (int idx = tid; idx < 1024; idx += 160) {
        int l = idx >> 4, n = idx & 15;
        g_Bm[(size_t)(bl0 + l) * DS + n] = dbl_s[l*41 + 8  + n];
        g_Cm[(size_t)(bl0 + l) * DS + n] = dbl_s[l*41 + 24 + n];
    }
    for (int idx = tid; idx < 64*256; idx += 160) {
        int l = idx >> 8, d = idx & 255;
        float a = bdt_s[d];
#pragma unroll
        for (int r = 0; r < 8; r++)
            a = fmaf(dbl_s[l*41 + r], Wdt_s[r*256 + d], a);
        float sp = (a > 20.f) ? a : log1pf(__expf(a));
        g_delta[(size_t)(bl0 + l) * DI + d] = sp;
    }
}

// ============ Scan pass A: per-chunk local final state + chunk decay =======
// grid (NC, NB), 256 threads, thread = one d with all 16 states in registers.
__global__ __launch_bounds__(256) void k_scanA(const float* __restrict__ A_log)
{
    __shared__ float sB[CT*DS];      // 4KB
    int d = threadIdx.x;
    int c = blockIdx.x;
    int b = blockIdx.y;
    int l0 = c * CT;

    // stage B tile
    for (int i = d; i < CT*DS/4; i += 256)
        *(float4*)&sB[i*4] = *(const float4*)(g_Bm + ((size_t)(b*LSEQ + l0))*DS + i*4);

    float a[DS];
#pragma unroll
    for (int g = 0; g < 4; g++) {
        float4 v = *(const float4*)(A_log + d*DS + g*4);
        a[g*4+0] = -__expf(v.x); a[g*4+1] = -__expf(v.y);
        a[g*4+2] = -__expf(v.z); a[g*4+3] = -__expf(v.w);
    }
    float h[DS];
#pragma unroll
    for (int n = 0; n < DS; n++) h[n] = 0.f;
    float S = 0.f;

    const float* pdt = g_delta + ((size_t)(b*LSEQ + l0))*DI + d;
    const float* pu  = g_xc    + ((size_t)(b*LSEQ + l0))*DI + d;
    float dtc = pdt[0], uc = pu[0];
    __syncthreads();

#pragma unroll 1
    for (int t = 0; t < CT; t++) {
        float dt = dtc, uu = uc;
        int tn = (t < CT-1) ? t+1 : t;
        dtc = pdt[(size_t)tn*DI];
        uc  = pu [(size_t)tn*DI];
        S += dt;
        float du = dt * uu;
        const float4* Bt = (const float4*)&sB[t*DS];
#pragma unroll
        for (int g = 0; g < 4; g++) {
            float4 b4 = Bt[g];
            h[g*4+0] = fmaf(__expf(dt*a[g*4+0]), h[g*4+0], du*b4.x);
            h[g*4+1] = fmaf(__expf(dt*a[g*4+1]), h[g*4+1], du*b4.y);
            h[g*4+2] = fmaf(__expf(dt*a[g*4+2]), h[g*4+2], du*b4.z);
            h[g*4+3] = fmaf(__expf(dt*a[g*4+3]), h[g*4+3], du*b4.w);
        }
    }
    size_t base = ((size_t)(b*NC + c)*DI + d)*DS;
#pragma unroll
    for (int g = 0; g < 4; g++) {
        *(float4*)(g_hfin + base + g*4) = make_float4(h[g*4+0], h[g*4+1], h[g*4+2], h[g*4+3]);
        *(float4*)(g_P + base + g*4) = make_float4(__expf(a[g*4+0]*S), __expf(a[g*4+1]*S),
                                                   __expf(a[g*4+2]*S), __expf(a[g*4+3]*S));
    }
}

// ============ Scan pass B: sequential chunk-state propagation ==============
__global__ __launch_bounds__(512) void k_scanB()
{
    int b  = blockIdx.x;
    int dn = blockIdx.y * 512 + threadIdx.x;   // 0..4095 = d*16+n
    float hs = 0.f;
    size_t base = (size_t)b * NC * (DI*DS) + dn;
#pragma unroll 1
    for (int c = 0; c < NC; c++) {
        size_t idx = base + (size_t)c * (DI*DS);
        g_hstart[idx] = hs;
        hs = fmaf(g_P[idx], hs, g_hfin[idx]);
    }
}

// ============ Scan pass C: replay chunk with correct start state, emit y ===
__global__ __launch_bounds__(256) void k_scanC(const float* __restrict__ A_log,
                                               const float* __restrict__ Dpar)
{
    __shared__ float sB[CT*DS];
    __shared__ float sC[CT*DS];
    int d = threadIdx.x;
    int c = blockIdx.x;
    int b = blockIdx.y;
    int l0 = c * CT;

    for (int i = d; i < CT*DS/4; i += 256) {
        *(float4*)&sB[i*4] = *(const float4*)(g_Bm + ((size_t)(b*LSEQ + l0))*DS + i*4);
        *(float4*)&sC[i*4] = *(const float4*)(g_Cm + ((size_t)(b*LSEQ + l0))*DS + i*4);
    }

    float a[DS];
#pragma unroll
    for (int g = 0; g < 4; g++) {
        float4 v = *(const float4*)(A_log + d*DS + g*4);
        a[g*4+0] = -__expf(v.x); a[g*4+1] = -__expf(v.y);
        a[g*4+2] = -__expf(v.z); a[g*4+3] = -__expf(v.w);
    }
    float Dp = Dpar[d];
    float h[DS];
    size_t hbase = ((size_t)(b*NC + c)*DI + d)*DS;
#pragma unroll
    for (int g = 0; g < 4; g++) {
        float4 v = *(const float4*)(g_hstart + hbase + g*4);
        h[g*4+0] = v.x; h[g*4+1] = v.y; h[g*4+2] = v.z; h[g*4+3] = v.w;
    }

    const float* pdt = g_delta + ((size_t)(b*LSEQ + l0))*DI + d;
    const float* pu  = g_xc    + ((size_t)(b*LSEQ + l0))*DI + d;
    const float* pz  = g_z     + ((size_t)(b*LSEQ + l0))*DI + d;
    float*       py  = g_y     + ((size_t)(b*LSEQ + l0))*DI + d;
    float dtc = pdt[0], uc = pu[0], zc = pz[0];
    __syncthreads();

#pragma unroll 1
    for (int t = 0; t < CT; t++) {
        float dt = dtc, uu = uc, zz = zc;
        int tn = (t < CT-1) ? t+1 : t;
        dtc = pdt[(size_t)tn*DI];
        uc  = pu [(size_t)tn*DI];
        zc  = pz [(size_t)tn*DI];
        float du = dt * uu;
        const float4* Bt = (const float4*)&sB[t*DS];
        const float4* Ct = (const float4*)&sC[t*DS];
        float y0 = 0.f, y1 = 0.f, y2 = 0.f, y3 = 0.f;
#pragma unroll
        for (int g = 0; g < 4; g++) {
            float4 b4 = Bt[g];
            float4 c4 = Ct[g];
            h[g*4+0] = fmaf(__expf(dt*a[g*4+0]), h[g*4+0], du*b4.x);
            h[g*4+1] = fmaf(__expf(dt*a[g*4+1]), h[g*4+1], du*b4.y);
            h[g*4+2] = fmaf(__expf(dt*a[g*4+2]), h[g*4+2], du*b4.z);
            h[g*4+3] = fmaf(__expf(dt*a[g*4+3]), h[g*4+3], du*b4.w);
            y0 = fmaf(h[g*4+0], c4.x, y0);
            y1 = fmaf(h[g*4+1], c4.y, y1);
            y2 = fmaf(h[g*4+2], c4.z, y2);
            y3 = fmaf(h[g*4+3], c4.w, y3);
        }
        float y = (y0 + y1) + (y2 + y3);
        y = (y + uu * Dp) * (zz * sigmoidf_(zz));
        py[(size_t)t*DI] = y;
    }
}

// ============ Kernel 5: out = y @ W_out, transposed store out[b,c,w,h] =====
__global__ __launch_bounds__(256) void k_outproj(const float* __restrict__ Wout,
                                                 float* __restrict__ out)
{
    __shared__ float As[64*65];
    __shared__ float Bs[64][64];
    int tid = threadIdx.x;
    int ty = tid >> 4, tx = tid & 15;
    int c0 = blockIdx.x * 64;
    int w  = blockIdx.y;
    int b  = blockIdx.z;

    float acc[4][4];
#pragma unroll
    for (int i = 0; i < 4; i++)
#pragma unroll
        for (int j = 0; j < 4; j++) acc[i][j] = 0.f;

    for (int kc = 0; kc < 4; kc++) {
#pragma unroll
        for (int it = 0; it < 4; it++) {
            int fid = tid + it*256;
            int m = fid >> 4, c4 = fid & 15;
            float4 v = *(const float4*)(g_y + (size_t)(b*LSEQ + m*64 + w) * DI + kc*64 + c4*4);
            As[m*65 + c4*4 + 0] = v.x;  As[m*65 + c4*4 + 1] = v.y;
            As[m*65 + c4*4 + 2] = v.z;  As[m*65 + c4*4 + 3] = v.w;
        }
#pragma unroll
        for (int it = 0; it < 4; it++) {
            int fid = tid + it*256;
            int r = fid >> 4, c4 = fid & 15;
            *(float4*)&Bs[r][c4*4] = *(const float4*)(Wout + (size_t)(kc*64 + r) * 128 + c0 + c4*4);
        }
        __syncthreads();
#pragma unroll
        for (int kk = 0; kk < 64; kk++) {
            float av[4];
#pragma unroll
            for (int i = 0; i < 4; i++) av[i] = As[(ty*4 + i)*65 + kk];
            float4 bq = *(const float4*)&Bs[kk][tx*4];
            float bv[4] = {bq.x, bq.y, bq.z, bq.w};
#pragma unroll
            for (int i = 0; i < 4; i++)
#pragma unroll
                for (int j = 0; j < 4; j++)
                    acc[i][j] = fmaf(av[i], bv[j], acc[i][j]);
        }
        __syncthreads();
    }
#pragma unroll
    for (int i = 0; i < 4; i++)
#pragma unroll
        for (int j = 0; j < 4; j++)
            As[(tx*4 + j)*65 + ty*4 + i] = acc[i][j];
    __syncthreads();
    for (int fid = tid; fid < 1024; fid += 256) {
        int c = fid >> 4, c4 = fid & 15;
        float4 v;
        v.x = As[c*65 + c4*4 + 0]; v.y = As[c*65 + c4*4 + 1];
        v.z = As[c*65 + c4*4 + 2]; v.w = As[c*65 + c4*4 + 3];
        *(float4*)(out + ((size_t)(b*128 + c0 + c)*64 + w)*64 + c4*4) = v;
    }
}

extern "C" void kernel_launch(void* const* d_in, const int* in_sizes, int n_in,
                              void* d_out, int out_size) {
    const float* x     = (const float*)d_in[0];
    const float* Win   = (const float*)d_in[1];
    const float* cw    = (const float*)d_in[2];
    const float* cb    = (const float*)d_in[3];
    const float* Wxp   = (const float*)d_in[4];
    const float* Wdt   = (const float*)d_in[5];
    const float* bdt   = (const float*)d_in[6];
    const float* A_log = (const float*)d_in[7];
    const float* Dpar  = (const float*)d_in[8];
    const float* Wout  = (const float*)d_in[9];
    float* out = (float*)d_out;

    k_inproj <<<dim3(1024, 8), 256>>>(x, Win);
    k_conv   <<<dim3(4, 32, 16), 256>>>(cw, cb);
    k_xproj  <<<dim3(1024), 160>>>(Wxp, Wdt, bdt);
    k_scanA  <<<dim3(NC, NB), 256>>>(A_log);
    k_scanB  <<<dim3(NB, 8), 512>>>();
    k_scanC  <<<dim3(NC, NB), 256>>>(A_log, Dpar);
    k_outproj<<<dim3(2, 64, 16), 256>>>(Wout, out);
}

// round 4
// speedup vs baseline: 2.1807x; 1.1564x over previous
#include <cuda_runtime.h>
#include <stdint.h>
#include <math.h>

#define DM    128
#define DI    256
#define DS    16
#define DR    8
#define NB    16
#define LSEQ  4096
#define BL    (NB*LSEQ)
#define CT    64
#define NC    (LSEQ/CT)

__device__ float g_xs[(size_t)BL*DI + DI];
__device__ float g_z [(size_t)BL*DI + DI];
__device__ float g_xc[(size_t)BL*DI + DI];
__device__ float g_delta[(size_t)BL*DI + DI];
__device__ float g_Bm[(size_t)BL*DS];
__device__ float g_Cm[(size_t)BL*DS];
__device__ float g_y [(size_t)BL*DI];
__device__ float g_hfin  [(size_t)NB*NC*DI*DS];
__device__ float g_P     [(size_t)NB*NC*DI*DS];
__device__ float g_hstart[(size_t)NB*NC*DI*DS];

__device__ __forceinline__ float sigmoidf_(float v){ return __fdividef(1.f, 1.f+__expf(-v)); }

__device__ __forceinline__ uint32_t f2tf(float f){
    uint32_t u; asm("cvt.rna.tf32.f32 %0, %1;" : "=r"(u) : "f"(f)); return u;
}
__device__ __forceinline__ void mma8(float* d, const uint32_t* a, const uint32_t* b){
    asm volatile("mma.sync.aligned.m16n8k8.row.col.f32.tf32.tf32.f32 "
        "{%0,%1,%2,%3},{%4,%5,%6,%7},{%8,%9},{%0,%1,%2,%3};"
        : "+f"(d[0]),"+f"(d[1]),"+f"(d[2]),"+f"(d[3])
        : "r"(a[0]),"r"(a[1]),"r"(a[2]),"r"(a[3]),"r"(b[0]),"r"(b[1]));
}
// e[n] = E^(n+1), n=0..15, depth-4 multiply chain
__device__ __forceinline__ void pow16(float E, float* e){
    float p2=E*E, p4=p2*p2, p8=p4*p4;
    e[0]=E;      e[1]=p2;     e[2]=p2*E;    e[3]=p4;
    e[4]=p4*E;   e[5]=p4*p2;  e[6]=p4*e[2]; e[7]=p8;
    e[8]=p8*E;   e[9]=p8*p2;  e[10]=p8*e[2];e[11]=p8*p4;
    e[12]=p8*e[4];e[13]=p8*e[5];e[14]=p8*e[6];e[15]=p8*p8;
}

// ======== Kernel 1: xz = u @ W_in, 3xTF32 mma (M=65536,N=512,K=128) ========
// BM=128, BN=64, BK=32; 256 thr = 8 warps (4m x 2n), warp tile 32x32.
__global__ __launch_bounds__(256) void k_inproj(const float* __restrict__ x,
                                                const float* __restrict__ Win)
{
    __shared__ float    As[32][136];          // [k][l], bank-safe (8k+l)
    __shared__ uint32_t Bhi[32][72], Blo[32][72];  // [k][n]
    int tid = threadIdx.x, lane = tid & 31, wid = tid >> 5;
    int warp_m = wid >> 1, warp_n = wid & 1;
    int mt = blockIdx.x;                 // 512 tiles of 128 rows
    int n0 = blockIdx.y * 64;            // 0..448
    int b  = mt >> 5;
    int l0 = (mt << 7) & 4095;
    const float* xb = x + (size_t)b * DM * LSEQ;

    float acc[2][4][4];
#pragma unroll
    for (int i=0;i<2;i++)
#pragma unroll
        for (int j=0;j<4;j++)
#pragma unroll
            for (int q=0;q<4;q++) acc[i][j][q]=0.f;

    for (int kc = 0; kc < 4; kc++) {
#pragma unroll
        for (int it = 0; it < 4; it++) {
            int fid = tid + it*256;
            int c = fid >> 5, lq = fid & 31;
            *(float4*)&As[c][lq*4] = *(const float4*)(xb + (size_t)(kc*32+c)*LSEQ + l0 + lq*4);
        }
#pragma unroll
        for (int it = 0; it < 2; it++) {
            int fid = tid + it*256;
            int k = fid >> 4, nq = fid & 15;
            float4 v = *(const float4*)(Win + (size_t)(kc*32+k)*512 + n0 + nq*4);
            float vv[4] = {v.x, v.y, v.z, v.w};
#pragma unroll
            for (int j = 0; j < 4; j++) {
                uint32_t hi = f2tf(vv[j]);
                Bhi[k][nq*4+j] = hi;
                Blo[k][nq*4+j] = f2tf(vv[j] - __uint_as_float(hi));
            }
        }
        __syncthreads();
#pragma unroll
        for (int ks = 0; ks < 4; ks++) {
            int k0 = ks*8;
            int col = k0 + (lane & 3);
            int rb  = warp_m*32 + (lane >> 2);
            uint32_t ahi[2][4], alo[2][4];
#pragma unroll
            for (int tm = 0; tm < 2; tm++) {
                int r0 = rb + tm*16;
                float a0 = As[col][r0],   a1 = As[col][r0+8];
                float a2 = As[col+4][r0], a3 = As[col+4][r0+8];
                ahi[tm][0]=f2tf(a0); alo[tm][0]=f2tf(a0-__uint_as_float(ahi[tm][0]));
                ahi[tm][1]=f2tf(a1); alo[tm][1]=f2tf(a1-__uint_as_float(ahi[tm][1]));
                ahi[tm][2]=f2tf(a2); alo[tm][2]=f2tf(a2-__uint_as_float(ahi[tm][2]));
                ahi[tm][3]=f2tf(a3); alo[tm][3]=f2tf(a3-__uint_as_float(ahi[tm][3]));
            }
            uint32_t bh[4][2], bl[4][2];
#pragma unroll
            for (int tn = 0; tn < 4; tn++) {
                int n = warp_n*32 + tn*8 + (lane >> 2);
                bh[tn][0] = Bhi[col][n];   bh[tn][1] = Bhi[col+4][n];
                bl[tn][0] = Blo[col][n];   bl[tn][1] = Blo[col+4][n];
            }
#pragma unroll
            for (int tm = 0; tm < 2; tm++)
#pragma unroll
                for (int tn = 0; tn < 4; tn++) {
                    mma8(acc[tm][tn], ahi[tm], bh[tn]);
                    mma8(acc[tm][tn], alo[tm], bh[tn]);
                    mma8(acc[tm][tn], ahi[tm], bl[tn]);
                }
        }
        __syncthreads();
    }
    float* dst = (n0 < 256) ? g_xs : g_z;
    int nb = (n0 < 256) ? n0 : (n0 - 256);
#pragma unroll
    for (int tm = 0; tm < 2; tm++) {
        int row = mt*128 + warp_m*32 + tm*16 + (lane >> 2);
#pragma unroll
        for (int tn = 0; tn < 4; tn++) {
            int colo = nb + warp_n*32 + tn*8 + (lane & 3)*2;
            *(float2*)(dst + (size_t)row*DI + colo)     = make_float2(acc[tm][tn][0], acc[tm][tn][1]);
            *(float2*)(dst + (size_t)(row+8)*DI + colo) = make_float2(acc[tm][tn][2], acc[tm][tn][3]);
        }
    }
}

// ============ Kernel 2: causal depthwise conv k=4 + bias + silu ============
__global__ __launch_bounds__(256) void k_conv(const float* __restrict__ cw,
                                              const float* __restrict__ cb)
{
    __shared__ float sx[131][64];
    __shared__ float scw[4][64];
    __shared__ float scb[64];
    int tid = threadIdx.x;
    int d0 = blockIdx.x * 64;
    int l0 = blockIdx.y * 128;
    int b  = blockIdx.z;

    if (tid < 64) {
        scb[tid] = cb[d0 + tid];
#pragma unroll
        for (int k = 0; k < 4; k++) scw[k][tid] = cw[(d0 + tid) * 4 + k];
    }
    for (int fid = tid; fid < 131*16; fid += 256) {
        int r = fid >> 4, c4 = fid & 15;
        int l = l0 - 3 + r;
        float4 v = make_float4(0.f, 0.f, 0.f, 0.f);
        if (l >= 0)
            v = *(const float4*)(g_xs + (size_t)(b*LSEQ + l) * DI + d0 + c4*4);
        *(float4*)&sx[r][c4*4] = v;
    }
    __syncthreads();
#pragma unroll
    for (int it = 0; it < 32; it++) {
        int idx = tid + it * 256;
        int li = idx >> 6, di = idx & 63;
        float v = scb[di];
#pragma unroll
        for (int k = 0; k < 4; k++) v = fmaf(scw[k][di], sx[li + k][di], v);
        v = v * sigmoidf_(v);
        g_xc[(size_t)(b*LSEQ + l0 + li) * DI + d0 + di] = v;
    }
}

// ============ Kernel 3: dbl = xc@W_xproj; delta = softplus(dt@W_dt+b) ======
__global__ __launch_bounds__(160) void k_xproj(const float* __restrict__ Wxp,
                                               const float* __restrict__ Wdt,
                                               const float* __restrict__ bdt)
{
    __shared__ float As[64*65];
    __shared__ float Bs[64*40];
    __shared__ float dbl_s[64*41];
    __shared__ float Wdt_s[8*256];
    __shared__ float bdt_s[256];
    int tid = threadIdx.x;
    int ty = tid / 10, tx = tid % 10;
    int bl0 = blockIdx.x * 64;

    for (int i = tid; i < 2048; i += 160) Wdt_s[i] = Wdt[i];
    for (int i = tid; i < 256;  i += 160) bdt_s[i] = bdt[i];

    float acc[4][4];
#pragma unroll
    for (int i = 0; i < 4; i++)
#pragma unroll
        for (int j = 0; j < 4; j++) acc[i][j] = 0.f;

    for (int kc = 0; kc < 4; kc++) {
        for (int fid = tid; fid < 1024; fid += 160) {
            int m = fid >> 4, c4 = fid & 15;
            float4 v = *(const float4*)(g_xc + (size_t)(bl0 + m) * DI + kc*64 + c4*4);
            As[m*65 + c4*4 + 0] = v.x;  As[m*65 + c4*4 + 1] = v.y;
            As[m*65 + c4*4 + 2] = v.z;  As[m*65 + c4*4 + 3] = v.w;
        }
        for (int fid = tid; fid < 640; fid += 160) {
            int k = fid / 10, c4 = fid % 10;
            *(float4*)&Bs[k*40 + c4*4] = *(const float4*)(Wxp + (size_t)(kc*64 + k) * 40 + c4*4);
        }
        __syncthreads();
#pragma unroll
        for (int kk = 0; kk < 64; kk++) {
            float av[4];
#pragma unroll
            for (int i = 0; i < 4; i++) av[i] = As[(ty*4 + i)*65 + kk];
            float4 bq = *(const float4*)&Bs[kk*40 + tx*4];
            float bv[4] = {bq.x, bq.y, bq.z, bq.w};
#pragma unroll
            for (int i = 0; i < 4; i++)
#pragma unroll
                for (int j = 0; j < 4; j++)
                    acc[i][j] = fmaf(av[i], bv[j], acc[i][j]);
        }
        __syncthreads();
    }
#pragma unroll
    for (int i = 0; i < 4; i++)
#pragma unroll
        for (int j = 0; j < 4; j++)
            dbl_s[(ty*4 + i)*41 + tx*4 + j] = acc[i][j];
    __syncthreads();

    for (int idx = tid; idx < 1024; idx += 160) {
        int l = idx >> 4, n = idx & 15;
        g_Bm[(size_t)(bl0 + l) * DS + n] = dbl_s[l*41 + 8  + n];
        g_Cm[(size_t)(bl0 + l) * DS + n] = dbl_s[l*41 + 24 + n];
    }
    for (int idx = tid; idx < 64*256; idx += 160) {
        int l = idx >> 8, d = idx & 255;
        float a = bdt_s[d];
#pragma unroll
        for (int r = 0; r < 8; r++)
            a = fmaf(dbl_s[l*41 + r], Wdt_s[r*256 + d], a);
        float sp = (a > 20.f) ? a : log1pf(__expf(a));
        g_delta[(size_t)(bl0 + l) * DI + d] = sp;
    }
}

// ============ Scan pass A ============
__global__ __launch_bounds__(256) void k_scanA(const float* __restrict__ A_log)
{
    __shared__ float sB[CT*DS];
    int d = threadIdx.x;
    int c = blockIdx.x;
    int b = blockIdx.y;
    int l0 = c * CT;

    for (int i = d; i < CT*DS/4; i += 256)
        *(float4*)&sB[i*4] = *(const float4*)(g_Bm + ((size_t)(b*LSEQ + l0))*DS + i*4);

    float a[DS];
#pragma unroll
    for (int g = 0; g < 4; g++) {
        float4 v = *(const float4*)(A_log + d*DS + g*4);
        a[g*4+0] = -__expf(v.x); a[g*4+1] = -__expf(v.y);
        a[g*4+2] = -__expf(v.z); a[g*4+3] = -__expf(v.w);
    }
    bool fast = true;
#pragma unroll
    for (int n = 0; n < DS; n++) {
        float r = a[n] / a[0];
        fast = fast && (fabsf(r - (float)(n+1)) < 1e-3f * (float)(n+1));
    }
    float a0v = a[0];
    float h[DS];
#pragma unroll
    for (int n = 0; n < DS; n++) h[n] = 0.f;
    float S = 0.f;

    const float* pdt = g_delta + ((size_t)(b*LSEQ + l0))*DI + d;
    const float* pu  = g_xc    + ((size_t)(b*LSEQ + l0))*DI + d;
    float dtc = pdt[0], uc = pu[0];
    __syncthreads();

    if (fast) {
#pragma unroll 1
        for (int t = 0; t < CT; t++) {
            float dt = dtc, uu = uc;
            int tn = (t < CT-1) ? t+1 : t;
            dtc = pdt[(size_t)tn*DI];
            uc  = pu [(size_t)tn*DI];
            S += dt;
            float du = dt * uu;
            float e[DS];
            pow16(__expf(dt*a0v), e);
            const float4* Bt = (const float4*)&sB[t*DS];
#pragma unroll
            for (int g = 0; g < 4; g++) {
                float4 b4 = Bt[g];
                h[g*4+0] = fmaf(e[g*4+0], h[g*4+0], du*b4.x);
                h[g*4+1] = fmaf(e[g*4+1], h[g*4+1], du*b4.y);
                h[g*4+2] = fmaf(e[g*4+2], h[g*4+2], du*b4.z);
                h[g*4+3] = fmaf(e[g*4+3], h[g*4+3], du*b4.w);
            }
        }
    } else {
#pragma unroll 1
        for (int t = 0; t < CT; t++) {
            float dt = dtc, uu = uc;
            int tn = (t < CT-1) ? t+1 : t;
            dtc = pdt[(size_t)tn*DI];
            uc  = pu [(size_t)tn*DI];
            S += dt;
            float du = dt * uu;
            const float4* Bt = (const float4*)&sB[t*DS];
#pragma unroll
            for (int g = 0; g < 4; g++) {
                float4 b4 = Bt[g];
                h[g*4+0] = fmaf(__expf(dt*a[g*4+0]), h[g*4+0], du*b4.x);
                h[g*4+1] = fmaf(__expf(dt*a[g*4+1]), h[g*4+1], du*b4.y);
                h[g*4+2] = fmaf(__expf(dt*a[g*4+2]), h[g*4+2], du*b4.z);
                h[g*4+3] = fmaf(__expf(dt*a[g*4+3]), h[g*4+3], du*b4.w);
            }
        }
    }
    float P[DS];
    if (fast) {
        pow16(__expf(S*a0v), P);
    } else {
#pragma unroll
        for (int n = 0; n < DS; n++) P[n] = __expf(a[n]*S);
    }
    size_t base = ((size_t)(b*NC + c)*DI + d)*DS;
#pragma unroll
    for (int g = 0; g < 4; g++) {
        *(float4*)(g_hfin + base + g*4) = make_float4(h[g*4+0], h[g*4+1], h[g*4+2], h[g*4+3]);
        *(float4*)(g_P    + base + g*4) = make_float4(P[g*4+0], P[g*4+1], P[g*4+2], P[g*4+3]);
    }
}

// ============ Scan pass B ============
__global__ __launch_bounds__(512) void k_scanB()
{
    int b  = blockIdx.x;
    int dn = blockIdx.y * 512 + threadIdx.x;
    float hs = 0.f;
    size_t base = (size_t)b * NC * (DI*DS) + dn;
#pragma unroll 1
    for (int c = 0; c < NC; c++) {
        size_t idx = base + (size_t)c * (DI*DS);
        g_hstart[idx] = hs;
        hs = fmaf(g_P[idx], hs, g_hfin[idx]);
    }
}

// ============ Scan pass C ============
__global__ __launch_bounds__(256) void k_scanC(const float* __restrict__ A_log,
                                               const float* __restrict__ Dpar)
{
    __shared__ float sB[CT*DS];
    __shared__ float sC[CT*DS];
    int d = threadIdx.x;
    int c = blockIdx.x;
    int b = blockIdx.y;
    int l0 = c * CT;

    for (int i = d; i < CT*DS/4; i += 256) {
        *(float4*)&sB[i*4] = *(const float4*)(g_Bm + ((size_t)(b*LSEQ + l0))*DS + i*4);
        *(float4*)&sC[i*4] = *(const float4*)(g_Cm + ((size_t)(b*LSEQ + l0))*DS + i*4);
    }

    float a[DS];
#pragma unroll
    for (int g = 0; g < 4; g++) {
        float4 v = *(const float4*)(A_log + d*DS + g*4);
        a[g*4+0] = -__expf(v.x); a[g*4+1] = -__expf(v.y);
        a[g*4+2] = -__expf(v.z); a[g*4+3] = -__expf(v.w);
    }
    bool fast = true;
#pragma unroll
    for (int n = 0; n < DS; n++) {
        float r = a[n] / a[0];
        fast = fast && (fabsf(r - (float)(n+1)) < 1e-3f * (float)(n+1));
    }
    float a0v = a[0];
    float Dp = Dpar[d];
    float h[DS];
    size_t hbase = ((size_t)(b*NC + c)*DI + d)*DS;
#pragma unroll
    for (int g = 0; g < 4; g++) {
        float4 v = *(const float4*)(g_hstart + hbase + g*4);
        h[g*4+0] = v.x; h[g*4+1] = v.y; h[g*4+2] = v.z; h[g*4+3] = v.w;
    }

    const float* pdt = g_delta + ((size_t)(b*LSEQ + l0))*DI + d;
    const float* pu  = g_xc    + ((size_t)(b*LSEQ + l0))*DI + d;
    const float* pz  = g_z     + ((size_t)(b*LSEQ + l0))*DI + d;
    float*       py  = g_y     + ((size_t)(b*LSEQ + l0))*DI + d;
    float dtc = pdt[0], uc = pu[0], zc = pz[0];
    __syncthreads();

    if (fast) {
#pragma unroll 1
        for (int t = 0; t < CT; t++) {
            float dt = dtc, uu = uc, zz = zc;
            int tn = (t < CT-1) ? t+1 : t;
            dtc = pdt[(size_t)tn*DI];
            uc  = pu [(size_t)tn*DI];
            zc  = pz [(size_t)tn*DI];
            float du = dt * uu;
            float e[DS];
            pow16(__expf(dt*a0v), e);
            const float4* Bt = (const float4*)&sB[t*DS];
            const float4* Ct = (const float4*)&sC[t*DS];
            float y0 = 0.f, y1 = 0.f, y2 = 0.f, y3 = 0.f;
#pragma unroll
            for (int g = 0; g < 4; g++) {
                float4 b4 = Bt[g];
                float4 c4 = Ct[g];
                h[g*4+0] = fmaf(e[g*4+0], h[g*4+0], du*b4.x);
                h[g*4+1] = fmaf(e[g*4+1], h[g*4+1], du*b4.y);
                h[g*4+2] = fmaf(e[g*4+2], h[g*4+2], du*b4.z);
                h[g*4+3] = fmaf(e[g*4+3], h[g*4+3], du*b4.w);
                y0 = fmaf(h[g*4+0], c4.x, y0);
                y1 = fmaf(h[g*4+1], c4.y, y1);
                y2 = fmaf(h[g*4+2], c4.z, y2);
                y3 = fmaf(h[g*4+3], c4.w, y3);
            }
            float y = (y0 + y1) + (y2 + y3);
            y = (y + uu * Dp) * (zz * sigmoidf_(zz));
            py[(size_t)t*DI] = y;
        }
    } else {
#pragma unroll 1
        for (int t = 0; t < CT; t++) {
            float dt = dtc, uu = uc, zz = zc;
            int tn = (t < CT-1) ? t+1 : t;
            dtc = pdt[(size_t)tn*DI];
            uc  = pu [(size_t)tn*DI];
            zc  = pz [(size_t)tn*DI];
            float du = dt * uu;
            const float4* Bt = (const float4*)&sB[t*DS];
            const float4* Ct = (const float4*)&sC[t*DS];
            float y0 = 0.f, y1 = 0.f, y2 = 0.f, y3 = 0.f;
#pragma unroll
            for (int g = 0; g < 4; g++) {
                float4 b4 = Bt[g];
                float4 c4 = Ct[g];
                h[g*4+0] = fmaf(__expf(dt*a[g*4+0]), h[g*4+0], du*b4.x);
                h[g*4+1] = fmaf(__expf(dt*a[g*4+1]), h[g*4+1], du*b4.y);
                h[g*4+2] = fmaf(__expf(dt*a[g*4+2]), h[g*4+2], du*b4.z);
                h[g*4+3] = fmaf(__expf(dt*a[g*4+3]), h[g*4+3], du*b4.w);
                y0 = fmaf(h[g*4+0], c4.x, y0);
                y1 = fmaf(h[g*4+1], c4.y, y1);
                y2 = fmaf(h[g*4+2], c4.z, y2);
                y3 = fmaf(h[g*4+3], c4.w, y3);
            }
            float y = (y0 + y1) + (y2 + y3);
            y = (y + uu * Dp) * (zz * sigmoidf_(zz));
            py[(size_t)t*DI] = y;
        }
    }
}

// ======== Kernel 5: out = y @ W_out (3xTF32), transposed store =============
// BM=64 (h), BN=128 (c), K=256; block = (w, b); 256 thr, warp tile 32x32.
__global__ __launch_bounds__(256) void k_outproj(const float* __restrict__ Wout,
                                                 float* __restrict__ out)
{
    __shared__ __align__(16) float sm[11264];
    float    (*As)[40]  = (float(*)[40])sm;                    // 64x40 = 2560
    uint32_t (*Bh)[136] = (uint32_t(*)[136])(sm + 2560);       // 32x136 = 4352
    uint32_t (*Bl)[136] = (uint32_t(*)[136])(sm + 2560 + 4352);
    float    (*Ds)[68]  = (float(*)[68])sm;                    // 128x68 = 8704

    int tid = threadIdx.x, lane = tid & 31, wid = tid >> 5;
    int warp_m = wid >> 2, warp_n = wid & 3;   // 2m x 4n
    int w = blockIdx.x;
    int b = blockIdx.y;

    float acc[2][4][4];
#pragma unroll
    for (int i=0;i<2;i++)
#pragma unroll
        for (int j=0;j<4;j++)
#pragma unroll
            for (int q=0;q<4;q++) acc[i][j][q]=0.f;

    for (int kc = 0; kc < 8; kc++) {
#pragma unroll
        for (int it = 0; it < 2; it++) {
            int fid = tid + it*256;
            int hh = fid >> 3, kq = fid & 7;
            *(float4*)&As[hh][kq*4] =
                *(const float4*)(g_y + (size_t)(b*LSEQ + hh*64 + w)*DI + kc*32 + kq*4);
        }
#pragma unroll
        for (int it = 0; it < 4; it++) {
            int fid = tid + it*256;
            int k = fid >> 5, nq = fid & 31;
            float4 v = *(const float4*)(Wout + (size_t)(kc*32+k)*128 + nq*4);
            float vv[4] = {v.x, v.y, v.z, v.w};
#pragma unroll
            for (int j = 0; j < 4; j++) {
                uint32_t hi = f2tf(vv[j]);
                Bh[k][nq*4+j] = hi;
                Bl[k][nq*4+j] = f2tf(vv[j] - __uint_as_float(hi));
            }
        }
        __syncthreads();
#pragma unroll
        for (int ks = 0; ks < 4; ks++) {
            int k0 = ks*8;
            int col = k0 + (lane & 3);
            int rb  = warp_m*32 + (lane >> 2);
            uint32_t ahi[2][4], alo[2][4];
#pragma unroll
            for (int tm = 0; tm < 2; tm++) {
                int r0 = rb + tm*16;
                float a0 = As[r0][col],   a1 = As[r0+8][col];
                float a2 = As[r0][col+4], a3 = As[r0+8][col+4];
                ahi[tm][0]=f2tf(a0); alo[tm][0]=f2tf(a0-__uint_as_float(ahi[tm][0]));
                ahi[tm][1]=f2tf(a1); alo[tm][1]=f2tf(a1-__uint_as_float(ahi[tm][1]));
                ahi[tm][2]=f2tf(a2); alo[tm][2]=f2tf(a2-__uint_as_float(ahi[tm][2]));
                ahi[tm][3]=f2tf(a3); alo[tm][3]=f2tf(a3-__uint_as_float(ahi[tm][3]));
            }
            uint32_t bh[4][2], bl[4][2];
#pragma unroll
            for (int tn = 0; tn < 4; tn++) {
                int n = warp_n*32 + tn*8 + (lane >> 2);
                bh[tn][0] = Bh[col][n];   bh[tn][1] = Bh[col+4][n];
                bl[tn][0] = Bl[col][n];   bl[tn][1] = Bl[col+4][n];
            }
#pragma unroll
            for (int tm = 0; tm < 2; tm++)
#pragma unroll
                for (int tn = 0; tn < 4; tn++) {
                    mma8(acc[tm][tn], ahi[tm], bh[tn]);
                    mma8(acc[tm][tn], alo[tm], bh[tn]);
                    mma8(acc[tm][tn], ahi[tm], bl[tn]);
                }
        }
        __syncthreads();
    }
    // stage transposed Ds[c][h]
#pragma unroll
    for (int tm = 0; tm < 2; tm++) {
        int hh = warp_m*32 + tm*16 + (lane >> 2);
#pragma unroll
        for (int tn = 0; tn < 4; tn++) {
            int cc = warp_n*32 + tn*8 + (lane & 3)*2;
            Ds[cc][hh]     = acc[tm][tn][0];
            Ds[cc+1][hh]   = acc[tm][tn][1];
            Ds[cc][hh+8]   = acc[tm][tn][2];
            Ds[cc+1][hh+8] = acc[tm][tn][3];
        }
    }
    __syncthreads();
#pragma unroll
    for (int it = 0; it < 8; it++) {
        int fid = tid + it*256;
        int cc = fid >> 4, hq = fid & 15;
        float4 v;
        v.x = Ds[cc][hq*4+0]; v.y = Ds[cc][hq*4+1];
        v.z = Ds[cc][hq*4+2]; v.w = Ds[cc][hq*4+3];
        *(float4*)(out + ((size_t)(b*128 + cc)*64 + w)*64 + hq*4) = v;
    }
}

extern "C" void kernel_launch(void* const* d_in, const int* in_sizes, int n_in,
                              void* d_out, int out_size) {
    const float* x     = (const float*)d_in[0];
    const float* Win   = (const float*)d_in[1];
    const float* cw    = (const float*)d_in[2];
    const float* cb    = (const float*)d_in[3];
    const float* Wxp   = (const float*)d_in[4];
    const float* Wdt   = (const float*)d_in[5];
    const float* bdt   = (const float*)d_in[6];
    const float* A_log = (const float*)d_in[7];
    const float* Dpar  = (const float*)d_in[8];
    const float* Wout  = (const float*)d_in[9];
    float* out = (float*)d_out;

    k_inproj <<<dim3(512, 8), 256>>>(x, Win);
    k_conv   <<<dim3(4, 32, 16), 256>>>(cw, cb);
    k_xproj  <<<dim3(1024), 160>>>(Wxp, Wdt, bdt);
    k_scanA  <<<dim3(NC, NB), 256>>>(A_log);
    k_scanB  <<<dim3(NB, 8), 512>>>();
    k_scanC  <<<dim3(NC, NB), 256>>>(A_log, Dpar);
    k_outproj<<<dim3(64, 16), 256>>>(Wout, out);
}

// round 5
// speedup vs baseline: 2.1996x; 1.0087x over previous
#include <cuda_runtime.h>
#include <stdint.h>
#include <math.h>

#define DM    128
#define DI    256
#define DS    16
#define DR    8
#define NB    16
#define LSEQ  4096
#define BL    (NB*LSEQ)
#define CT    64
#define NC    (LSEQ/CT)

__device__ float g_xs[(size_t)BL*DI + DI];
__device__ float g_z [(size_t)BL*DI + DI];
__device__ float g_xc[(size_t)BL*DI + DI];
__device__ float g_delta[(size_t)BL*DI + DI];
__device__ float g_Bm[(size_t)BL*DS];
__device__ float g_Cm[(size_t)BL*DS];
__device__ float g_y [(size_t)BL*DI];
__device__ float g_hfin  [(size_t)NB*NC*DI*DS];
__device__ float g_P     [(size_t)NB*NC*DI*DS];
__device__ float g_hstart[(size_t)NB*NC*DI*DS];

__device__ __forceinline__ float sigmoidf_(float v){ return __fdividef(1.f, 1.f+__expf(-v)); }

__device__ __forceinline__ uint32_t f2tf(float f){
    uint32_t u; asm("cvt.rna.tf32.f32 %0, %1;" : "=r"(u) : "f"(f)); return u;
}
__device__ __forceinline__ void mma8(float* d, const uint32_t* a, const uint32_t* b){
    asm volatile("mma.sync.aligned.m16n8k8.row.col.f32.tf32.tf32.f32 "
        "{%0,%1,%2,%3},{%4,%5,%6,%7},{%8,%9},{%0,%1,%2,%3};"
        : "+f"(d[0]),"+f"(d[1]),"+f"(d[2]),"+f"(d[3])
        : "r"(a[0]),"r"(a[1]),"r"(a[2]),"r"(a[3]),"r"(b[0]),"r"(b[1]));
}
// e[n] = E^(n+1), n=0..15, depth-4 multiply chain
__device__ __forceinline__ void pow16(float E, float* e){
    float p2=E*E, p4=p2*p2, p8=p4*p4;
    e[0]=E;      e[1]=p2;     e[2]=p2*E;    e[3]=p4;
    e[4]=p4*E;   e[5]=p4*p2;  e[6]=p4*e[2]; e[7]=p8;
    e[8]=p8*E;   e[9]=p8*p2;  e[10]=p8*e[2];e[11]=p8*p4;
    e[12]=p8*e[4];e[13]=p8*e[5];e[14]=p8*e[6];e[15]=p8*p8;
}

// ======== Kernel 1: xz = u @ W_in, 3xTF32 mma (M=65536,N=512,K=128) ========
// BM=128, BN=64, BK=32; 256 thr = 8 warps (4m x 2n), warp tile 32x32.
__global__ __launch_bounds__(256) void k_inproj(const float* __restrict__ x,
                                                const float* __restrict__ Win)
{
    __shared__ float    As[32][136];          // [k][l], bank-safe (8k+l)
    __shared__ uint32_t Bhi[32][72], Blo[32][72];  // [k][n]
    int tid = threadIdx.x, lane = tid & 31, wid = tid >> 5;
    int warp_m = wid >> 1, warp_n = wid & 1;
    int mt = blockIdx.x;                 // 512 tiles of 128 rows
    int n0 = blockIdx.y * 64;            // 0..448
    int b  = mt >> 5;
    int l0 = (mt << 7) & 4095;
    const float* xb = x + (size_t)b * DM * LSEQ;

    float acc[2][4][4];
#pragma unroll
    for (int i=0;i<2;i++)
#pragma unroll
        for (int j=0;j<4;j++)
#pragma unroll
            for (int q=0;q<4;q++) acc[i][j][q]=0.f;

    for (int kc = 0; kc < 4; kc++) {
#pragma unroll
        for (int it = 0; it < 4; it++) {
            int fid = tid + it*256;
            int c = fid >> 5, lq = fid & 31;
            *(float4*)&As[c][lq*4] = *(const float4*)(xb + (size_t)(kc*32+c)*LSEQ + l0 + lq*4);
        }
#pragma unroll
        for (int it = 0; it < 2; it++) {
            int fid = tid + it*256;
            int k = fid >> 4, nq = fid & 15;
            float4 v = *(const float4*)(Win + (size_t)(kc*32+k)*512 + n0 + nq*4);
            float vv[4] = {v.x, v.y, v.z, v.w};
#pragma unroll
            for (int j = 0; j < 4; j++) {
                uint32_t hi = f2tf(vv[j]);
                Bhi[k][nq*4+j] = hi;
                Blo[k][nq*4+j] = f2tf(vv[j] - __uint_as_float(hi));
            }
        }
        __syncthreads();
#pragma unroll
        for (int ks = 0; ks < 4; ks++) {
            int k0 = ks*8;
            int col = k0 + (lane & 3);
            int rb  = warp_m*32 + (lane >> 2);
            uint32_t ahi[2][4], alo[2][4];
#pragma unroll
            for (int tm = 0; tm < 2; tm++) {
                int r0 = rb + tm*16;
                float a0 = As[col][r0],   a1 = As[col][r0+8];
                float a2 = As[col+4][r0], a3 = As[col+4][r0+8];
                ahi[tm][0]=f2tf(a0); alo[tm][0]=f2tf(a0-__uint_as_float(ahi[tm][0]));
                ahi[tm][1]=f2tf(a1); alo[tm][1]=f2tf(a1-__uint_as_float(ahi[tm][1]));
                ahi[tm][2]=f2tf(a2); alo[tm][2]=f2tf(a2-__uint_as_float(ahi[tm][2]));
                ahi[tm][3]=f2tf(a3); alo[tm][3]=f2tf(a3-__uint_as_float(ahi[tm][3]));
            }
            uint32_t bh[4][2], bl[4][2];
#pragma unroll
            for (int tn = 0; tn < 4; tn++) {
                int n = warp_n*32 + tn*8 + (lane >> 2);
                bh[tn][0] = Bhi[col][n];   bh[tn][1] = Bhi[col+4][n];
                bl[tn][0] = Blo[col][n];   bl[tn][1] = Blo[col+4][n];
            }
#pragma unroll
            for (int tm = 0; tm < 2; tm++)
#pragma unroll
                for (int tn = 0; tn < 4; tn++) {
                    mma8(acc[tm][tn], ahi[tm], bh[tn]);
                    mma8(acc[tm][tn], alo[tm], bh[tn]);
                    mma8(acc[tm][tn], ahi[tm], bl[tn]);
                }
        }
        __syncthreads();
    }
    float* dst = (n0 < 256) ? g_xs : g_z;
    int nb = (n0 < 256) ? n0 : (n0 - 256);
#pragma unroll
    for (int tm = 0; tm < 2; tm++) {
        int row = mt*128 + warp_m*32 + tm*16 + (lane >> 2);
#pragma unroll
        for (int tn = 0; tn < 4; tn++) {
            int colo = nb + warp_n*32 + tn*8 + (lane & 3)*2;
            *(float2*)(dst + (size_t)row*DI + colo)     = make_float2(acc[tm][tn][0], acc[tm][tn][1]);
            *(float2*)(dst + (size_t)(row+8)*DI + colo) = make_float2(acc[tm][tn][2], acc[tm][tn][3]);
        }
    }
}

// ============ Kernel 2: causal depthwise conv k=4 + bias + silu ============
__global__ __launch_bounds__(256) void k_conv(const float* __restrict__ cw,
                                              const float* __restrict__ cb)
{
    __shared__ float sx[131][64];
    __shared__ float scw[4][64];
    __shared__ float scb[64];
    int tid = threadIdx.x;
    int d0 = blockIdx.x * 64;
    int l0 = blockIdx.y * 128;
    int b  = blockIdx.z;

    if (tid < 64) {
        scb[tid] = cb[d0 + tid];
#pragma unroll
        for (int k = 0; k < 4; k++) scw[k][tid] = cw[(d0 + tid) * 4 + k];
    }
    for (int fid = tid; fid < 131*16; fid += 256) {
        int r = fid >> 4, c4 = fid & 15;
        int l = l0 - 3 + r;
        float4 v = make_float4(0.f, 0.f, 0.f, 0.f);
        if (l >= 0)
            v = *(const float4*)(g_xs + (size_t)(b*LSEQ + l) * DI + d0 + c4*4);
        *(float4*)&sx[r][c4*4] = v;
    }
    __syncthreads();
#pragma unroll
    for (int it = 0; it < 32; it++) {
        int idx = tid + it * 256;
        int li = idx >> 6, di = idx & 63;
        float v = scb[di];
#pragma unroll
        for (int k = 0; k < 4; k++) v = fmaf(scw[k][di], sx[li + k][di], v);
        v = v * sigmoidf_(v);
        g_xc[(size_t)(b*LSEQ + l0 + li) * DI + d0 + di] = v;
    }
}

// ============ Kernel 3: dbl = xc@W_xproj; delta = softplus(dt@W_dt+b) ======
__global__ __launch_bounds__(160) void k_xproj(const float* __restrict__ Wxp,
                                               const float* __restrict__ Wdt,
                                               const float* __restrict__ bdt)
{
    __shared__ float As[64*65];
    __shared__ float Bs[64*40];
    __shared__ float dbl_s[64*41];
    __shared__ float Wdt_s[8*256];
    __shared__ float bdt_s[256];
    int tid = threadIdx.x;
    int ty = tid / 10, tx = tid % 10;
    int bl0 = blockIdx.x * 64;

    for (int i = tid; i < 2048; i += 160) Wdt_s[i] = Wdt[i];
    for (int i = tid; i < 256;  i += 160) bdt_s[i] = bdt[i];

    float acc[4][4];
#pragma unroll
    for (int i = 0; i < 4; i++)
#pragma unroll
        for (int j = 0; j < 4; j++) acc[i][j] = 0.f;

    for (int kc = 0; kc < 4; kc++) {
        for (int fid = tid; fid < 1024; fid += 160) {
            int m = fid >> 4, c4 = fid & 15;
            float4 v = *(const float4*)(g_xc + (size_t)(bl0 + m) * DI + kc*64 + c4*4);
            As[m*65 + c4*4 + 0] = v.x;  As[m*65 + c4*4 + 1] = v.y;
            As[m*65 + c4*4 + 2] = v.z;  As[m*65 + c4*4 + 3] = v.w;
        }
        for (int fid = tid; fid < 640; fid += 160) {
            int k = fid / 10, c4 = fid % 10;
            *(float4*)&Bs[k*40 + c4*4] = *(const float4*)(Wxp + (size_t)(kc*64 + k) * 40 + c4*4);
        }
        __syncthreads();
#pragma unroll
        for (int kk = 0; kk < 64; kk++) {
            float av[4];
#pragma unroll
            for (int i = 0; i < 4; i++) av[i] = As[(ty*4 + i)*65 + kk];
            float4 bq = *(const float4*)&Bs[kk*40 + tx*4];
            float bv[4] = {bq.x, bq.y, bq.z, bq.w};
#pragma unroll
            for (int i = 0; i < 4; i++)
#pragma unroll
                for (int j = 0; j < 4; j++)
                    acc[i][j] = fmaf(av[i], bv[j], acc[i][j]);
        }
        __syncthreads();
    }
#pragma unroll
    for (int i = 0; i < 4; i++)
#pragma unroll
        for (int j = 0; j < 4; j++)
            dbl_s[(ty*4 + i)*41 + tx*4 + j] = acc[i][j];
    __syncthreads();

    for (int idx = tid; idx < 1024; idx += 160) {
        int l = idx >> 4, n = idx & 15;
        g_Bm[(size_t)(bl0 + l) * DS + n] = dbl_s[l*41 + 8  + n];
        g_Cm[(size_t)(bl0 + l) * DS + n] = dbl_s[l*41 + 24 + n];
    }
    for (int idx = tid; idx < 64*256; idx += 160) {
        int l = idx >> 8, d = idx & 255;
        float a = bdt_s[d];
#pragma unroll
        for (int r = 0; r < 8; r++)
            a = fmaf(dbl_s[l*41 + r], Wdt_s[r*256 + d], a);
        float sp = (a > 20.f) ? a : log1pf(__expf(a));
        g_delta[(size_t)(bl0 + l) * DI + d] = sp;
    }
}

// ============ Scan pass A ============
__global__ __launch_bounds__(256) void k_scanA(const float* __restrict__ A_log)
{
    __shared__ float sB[CT*DS];
    int d = threadIdx.x;
    int c = blockIdx.x;
    int b = blockIdx.y;
    int l0 = c * CT;

    for (int i = d; i < CT*DS/4; i += 256)
        *(float4*)&sB[i*4] = *(const float4*)(g_Bm + ((size_t)(b*LSEQ + l0))*DS + i*4);

    float a[DS];
#pragma unroll
    for (int g = 0; g < 4; g++) {
        float4 v = *(const float4*)(A_log + d*DS + g*4);
        a[g*4+0] = -__expf(v.x); a[g*4+1] = -__expf(v.y);
        a[g*4+2] = -__expf(v.z); a[g*4+3] = -__expf(v.w);
    }
    bool fast = true;
#pragma unroll
    for (int n = 0; n < DS; n++) {
        float r = a[n] / a[0];
        fast = fast && (fabsf(r - (float)(n+1)) < 1e-3f * (float)(n+1));
    }
    float a0v = a[0];
    float h[DS];
#pragma unroll
    for (int n = 0; n < DS; n++) h[n] = 0.f;
    float S = 0.f;

    const float* pdt = g_delta + ((size_t)(b*LSEQ + l0))*DI + d;
    const float* pu  = g_xc    + ((size_t)(b*LSEQ + l0))*DI + d;
    float dtc = pdt[0], uc = pu[0];
    __syncthreads();

    if (fast) {
#pragma unroll 1
        for (int t = 0; t < CT; t++) {
            float dt = dtc, uu = uc;
            int tn = (t < CT-1) ? t+1 : t;
            dtc = pdt[(size_t)tn*DI];
            uc  = pu [(size_t)tn*DI];
            S += dt;
            float du = dt * uu;
            float e[DS];
            pow16(__expf(dt*a0v), e);
            const float4* Bt = (const float4*)&sB[t*DS];
#pragma unroll
            for (int g = 0; g < 4; g++) {
                float4 b4 = Bt[g];
                h[g*4+0] = fmaf(e[g*4+0], h[g*4+0], du*b4.x);
                h[g*4+1] = fmaf(e[g*4+1], h[g*4+1], du*b4.y);
                h[g*4+2] = fmaf(e[g*4+2], h[g*4+2], du*b4.z);
                h[g*4+3] = fmaf(e[g*4+3], h[g*4+3], du*b4.w);
            }
        }
    } else {
#pragma unroll 1
        for (int t = 0; t < CT; t++) {
            float dt = dtc, uu = uc;
            int tn = (t < CT-1) ? t+1 : t;
            dtc = pdt[(size_t)tn*DI];
            uc  = pu [(size_t)tn*DI];
            S += dt;
            float du = dt * uu;
            const float4* Bt = (const float4*)&sB[t*DS];
#pragma unroll
            for (int g = 0; g < 4; g++) {
                float4 b4 = Bt[g];
                h[g*4+0] = fmaf(__expf(dt*a[g*4+0]), h[g*4+0], du*b4.x);
                h[g*4+1] = fmaf(__expf(dt*a[g*4+1]), h[g*4+1], du*b4.y);
                h[g*4+2] = fmaf(__expf(dt*a[g*4+2]), h[g*4+2], du*b4.z);
                h[g*4+3] = fmaf(__expf(dt*a[g*4+3]), h[g*4+3], du*b4.w);
            }
        }
    }
    float P[DS];
    if (fast) {
        pow16(__expf(S*a0v), P);
    } else {
#pragma unroll
        for (int n = 0; n < DS; n++) P[n] = __expf(a[n]*S);
    }
    size_t base = ((size_t)(b*NC + c)*DI + d)*DS;
#pragma unroll
    for (int g = 0; g < 4; g++) {
        *(float4*)(g_hfin + base + g*4) = make_float4(h[g*4+0], h[g*4+1], h[g*4+2], h[g*4+3]);
        *(float4*)(g_P    + base + g*4) = make_float4(P[g*4+0], P[g*4+1], P[g*4+2], P[g*4+3]);
    }
}

// ============ Scan pass B ============
__global__ __launch_bounds__(512) void k_scanB()
{
    int b  = blockIdx.x;
    int dn = blockIdx.y * 512 + threadIdx.x;
    float hs = 0.f;
    size_t base = (size_t)b * NC * (DI*DS) + dn;
#pragma unroll 1
    for (int c = 0; c < NC; c++) {
        size_t idx = base + (size_t)c * (DI*DS);
        g_hstart[idx] = hs;
        hs = fmaf(g_P[idx], hs, g_hfin[idx]);
    }
}

// ============ Scan pass C ============
__global__ __launch_bounds__(256) void k_scanC(const float* __restrict__ A_log,
                                               const float* __restrict__ Dpar)
{
    __shared__ float sB[CT*DS];
    __shared__ float sC[CT*DS];
    int d = threadIdx.x;
    int c = blockIdx.x;
    int b = blockIdx.y;
    int l0 = c * CT;

    for (int i = d; i < CT*DS/4; i += 256) {
        *(float4*)&sB[i*4] = *(const float4*)(g_Bm + ((size_t)(b*LSEQ + l0))*DS + i*4);
        *(float4*)&sC[i*4] = *(const float4*)(g_Cm + ((size_t)(b*LSEQ + l0))*DS + i*4);
    }

    float a[DS];
#pragma unroll
    for (int g = 0; g < 4; g++) {
        float4 v = *(const float4*)(A_log + d*DS + g*4);
        a[g*4+0] = -__expf(v.x); a[g*4+1] = -__expf(v.y);
        a[g*4+2] = -__expf(v.z); a[g*4+3] = -__expf(v.w);
    }
    bool fast = true;
#pragma unroll
    for (int n = 0; n < DS; n++) {
        float r = a[n] / a[0];
        fast = fast && (fabsf(r - (float)(n+1)) < 1e-3f * (float)(n+1));
    }
    float a0v = a[0];
    float Dp = Dpar[d];
    float h[DS];
    size_t hbase = ((size_t)(b*NC + c)*DI + d)*DS;
#pragma unroll
    for (int g = 0; g < 4; g++) {
        float4 v = *(const float4*)(g_hstart + hbase + g*4);
        h[g*4+0] = v.x; h[g*4+1] = v.y; h[g*4+2] = v.z; h[g*4+3] = v.w;
    }

    const float* pdt = g_delta + ((size_t)(b*LSEQ + l0))*DI + d;
    const float* pu  = g_xc    + ((size_t)(b*LSEQ + l0))*DI + d;
    const float* pz  = g_z     + ((size_t)(b*LSEQ + l0))*DI + d;
    float*       py  = g_y     + ((size_t)(b*LSEQ + l0))*DI + d;
    float dtc = pdt[0], uc = pu[0], zc = pz[0];
    __syncthreads();

    if (fast) {
#pragma unroll 1
        for (int t = 0; t < CT; t++) {
            float dt = dtc, uu = uc, zz = zc;
            int tn = (t < CT-1) ? t+1 : t;
            dtc = pdt[(size_t)tn*DI];
            uc  = pu [(size_t)tn*DI];
            zc  = pz [(size_t)tn*DI];
            float du = dt * uu;
            float e[DS];
            pow16(__expf(dt*a0v), e);
            const float4* Bt = (const float4*)&sB[t*DS];
            const float4* Ct = (const float4*)&sC[t*DS];
            float y0 = 0.f, y1 = 0.f, y2 = 0.f, y3 = 0.f;
#pragma unroll
            for (int g = 0; g < 4; g++) {
                float4 b4 = Bt[g];
                float4 c4 = Ct[g];
                h[g*4+0] = fmaf(e[g*4+0], h[g*4+0], du*b4.x);
                h[g*4+1] = fmaf(e[g*4+1], h[g*4+1], du*b4.y);
                h[g*4+2] = fmaf(e[g*4+2], h[g*4+2], du*b4.z);
                h[g*4+3] = fmaf(e[g*4+3], h[g*4+3], du*b4.w);
                y0 = fmaf(h[g*4+0], c4.x, y0);
                y1 = fmaf(h[g*4+1], c4.y, y1);
                y2 = fmaf(h[g*4+2], c4.z, y2);
                y3 = fmaf(h[g*4+3], c4.w, y3);
            }
            float y = (y0 + y1) + (y2 + y3);
            y = (y + uu * Dp) * (zz * sigmoidf_(zz));
            py[(size_t)t*DI] = y;
        }
    } else {
#pragma unroll 1
        for (int t = 0; t < CT; t++) {
            float dt = dtc, uu = uc, zz = zc;
            int tn = (t < CT-1) ? t+1 : t;
            dtc = pdt[(size_t)tn*DI];
            uc  = pu [(size_t)tn*DI];
            zc  = pz [(size_t)tn*DI];
            float du = dt * uu;
            const float4* Bt = (const float4*)&sB[t*DS];
            const float4* Ct = (const float4*)&sC[t*DS];
            float y0 = 0.f, y1 = 0.f, y2 = 0.f, y3 = 0.f;
#pragma unroll
            for (int g = 0; g < 4; g++) {
                float4 b4 = Bt[g];
                float4 c4 = Ct[g];
                h[g*4+0] = fmaf(__expf(dt*a[g*4+0]), h[g*4+0], du*b4.x);
                h[g*4+1] = fmaf(__expf(dt*a[g*4+1]), h[g*4+1], du*b4.y);
                h[g*4+2] = fmaf(__expf(dt*a[g*4+2]), h[g*4+2], du*b4.z);
                h[g*4+3] = fmaf(__expf(dt*a[g*4+3]), h[g*4+3], du*b4.w);
                y0 = fmaf(h[g*4+0], c4.x, y0);
                y1 = fmaf(h[g*4+1], c4.y, y1);
                y2 = fmaf(h[g*4+2], c4.z, y2);
                y3 = fmaf(h[g*4+3], c4.w, y3);
            }
            float y = (y0 + y1) + (y2 + y3);
            y = (y + uu * Dp) * (zz * sigmoidf_(zz));
            py[(size_t)t*DI] = y;
        }
    }
}

// ======== Kernel 5: out = y @ W_out (3xTF32), transposed store =============
// BM=64 (h), BN=128 (c), K=256; block = (w, b); 256 thr, warp tile 32x32.
__global__ __launch_bounds__(256) void k_outproj(const float* __restrict__ Wout,
                                                 float* __restrict__ out)
{
    __shared__ __align__(16) float sm[11264];
    float    (*As)[40]  = (float(*)[40])sm;                    // 64x40 = 2560
    uint32_t (*Bh)[136] = (uint32_t(*)[136])(sm + 2560);       // 32x136 = 4352
    uint32_t (*Bl)[136] = (uint32_t(*)[136])(sm + 2560 + 4352);
    float    (*Ds)[68]  = (float(*)[68])sm;                    // 128x68 = 8704

    int tid = threadIdx.x, lane = tid & 31, wid = tid >> 5;
    int warp_m = wid >> 2, warp_n = wid & 3;   // 2m x 4n
    int w = blockIdx.x;
    int b = blockIdx.y;

    float acc[2][4][4];
#pragma unroll
    for (int i=0;i<2;i++)
#pragma unroll
        for (int j=0;j<4;j++)
#pragma unroll
            for (int q=0;q<4;q++) acc[i][j][q]=0.f;

    for (int kc = 0; kc < 8; kc++) {
#pragma unroll
        for (int it = 0; it < 2; it++) {
            int fid = tid + it*256;
            int hh = fid >> 3, kq = fid & 7;
            *(float4*)&As[hh][kq*4] =
                *(const float4*)(g_y + (size_t)(b*LSEQ + hh*64 + w)*DI + kc*32 + kq*4);
        }
#pragma unroll
        for (int it = 0; it < 4; it++) {
            int fid = tid + it*256;
            int k = fid >> 5, nq = fid & 31;
            float4 v = *(const float4*)(Wout + (size_t)(kc*32+k)*128 + nq*4);
            float vv[4] = {v.x, v.y, v.z, v.w};
#pragma unroll
            for (int j = 0; j < 4; j++) {
                uint32_t hi = f2tf(vv[j]);
                Bh[k][nq*4+j] = hi;
                Bl[k][nq*4+j] = f2tf(vv[j] - __uint_as_float(hi));
            }
        }
        __syncthreads();
#pragma unroll
        for (int ks = 0; ks < 4; ks++) {
            int k0 = ks*8;
            int col = k0 + (lane & 3);
            int rb  = warp_m*32 + (lane >> 2);
            uint32_t ahi[2][4], alo[2][4];
#pragma unroll
            for (int tm = 0; tm < 2; tm++) {
                int r0 = rb + tm*16;
                float a0 = As[r0][col],   a1 = As[r0+8][col];
                float a2 = As[r0][col+4], a3 = As[r0+8][col+4];
                ahi[tm][0]=f2tf(a0); alo[tm][0]=f2tf(a0-__uint_as_float(ahi[tm][0]));
                ahi[tm][1]=f2tf(a1); alo[tm][1]=f2tf(a1-__uint_as_float(ahi[tm][1]));
                ahi[tm][2]=f2tf(a2); alo[tm][2]=f2tf(a2-__uint_as_float(ahi[tm][2]));
                ahi[tm][3]=f2tf(a3); alo[tm][3]=f2tf(a3-__uint_as_float(ahi[tm][3]));
            }
            uint32_t bh[4][2], bl[4][2];
#pragma unroll
            for (int tn = 0; tn < 4; tn++) {
                int n = warp_n*32 + tn*8 + (lane >> 2);
                bh[tn][0] = Bh[col][n];   bh[tn][1] = Bh[col+4][n];
                bl[tn][0] = Bl[col][n];   bl[tn][1] = Bl[col+4][n];
            }
#pragma unroll
            for (int tm = 0; tm < 2; tm++)
#pragma unroll
                for (int tn = 0; tn < 4; tn++) {
                    mma8(acc[tm][tn], ahi[tm], bh[tn]);
                    mma8(acc[tm][tn], alo[tm], bh[tn]);
                    mma8(acc[tm][tn], ahi[tm], bl[tn]);
                }
        }
        __syncthreads();
    }
    // stage transposed Ds[c][h]
#pragma unroll
    for (int tm = 0; tm < 2; tm++) {
        int hh = warp_m*32 + tm*16 + (lane >> 2);
#pragma unroll
        for (int tn = 0; tn < 4; tn++) {
            int cc = warp_n*32 + tn*8 + (lane & 3)*2;
            Ds[cc][hh]     = acc[tm][tn][0];
            Ds[cc+1][hh]   = acc[tm][tn][1];
            Ds[cc][hh+8]   = acc[tm][tn][2];
            Ds[cc+1][hh+8] = acc[tm][tn][3];
        }
    }
    __syncthreads();
#pragma unroll
    for (int it = 0; it < 8; it++) {
        int fid = tid + it*256;
        int cc = fid >> 4, hq = fid & 15;
        float4 v;
        v.x = Ds[cc][hq*4+0]; v.y = Ds[cc][hq*4+1];
        v.z = Ds[cc][hq*4+2]; v.w = Ds[cc][hq*4+3];
        *(float4*)(out + ((size_t)(b*128 + cc)*64 + w)*64 + hq*4) = v;
    }
}

extern "C" void kernel_launch(void* const* d_in, const int* in_sizes, int n_in,
                              void* d_out, int out_size) {
    const float* x     = (const float*)d_in[0];
    const float* Win   = (const float*)d_in[1];
    const float* cw    = (const float*)d_in[2];
    const float* cb    = (const float*)d_in[3];
    const float* Wxp   = (const float*)d_in[4];
    const float* Wdt   = (const float*)d_in[5];
    const float* bdt   = (const float*)d_in[6];
    const float* A_log = (const float*)d_in[7];
    const float* Dpar  = (const float*)d_in[8];
    const float* Wout  = (const float*)d_in[9];
    float* out = (float*)d_out;

    k_inproj <<<dim3(512, 8), 256>>>(x, Win);
    k_conv   <<<dim3(4, 32, 16), 256>>>(cw, cb);
    k_xproj  <<<dim3(1024), 160>>>(Wxp, Wdt, bdt);
    k_scanA  <<<dim3(NC, NB), 256>>>(A_log);
    k_scanB  <<<dim3(NB, 8), 512>>>();
    k_scanC  <<<dim3(NC, NB), 256>>>(A_log, Dpar);
    k_outproj<<<dim3(64, 16), 256>>>(Wout, out);
}